// round 14
// baseline (speedup 1.0000x reference)
#include <cuda_runtime.h>
#include <math.h>

// Problem constants
#define B_  4
#define C_  128
#define H_  192
#define W_  192
#define HW_ (H_ * W_)          // 36864
#define NH_ 2
#define D_  64
#define C3_ 384                 // 3 * C
#define NCHUNK 32
#define CHUNK  (HW_ / NCHUNK)   // 1152
#define NTILE  36               // 6x6 tiles of 32x32

// ---------------- scratch (device globals; no allocation allowed) -----------
__device__ float g_y[(size_t)2 * B_ * C3_ * HW_];          // 452 MB: post-leaky qkv conv (x, ir)
__device__ float g_spart[2 * B_ * C3_ * NTILE * 2];        // per-tile (sum, sumsq)
__device__ float g_scale[2 * B_ * C3_];                    // instancenorm scale
__device__ float g_off[2 * B_ * C3_];                      // instancenorm offset
__device__ float g_qkv[(size_t)3 * B_ * NH_ * D_ * HW_];   // 226 MB: q,k,v after fusion convs
__device__ float g_part[(size_t)NCHUNK * B_ * NH_ * D_ * D_]; // 4 MB: split-K GEMM partials
__device__ float g_rnorm[2 * B_ * NH_ * D_];               // q,k row norms
__device__ float g_attn[B_ * NH_ * D_ * D_];               // softmaxed attention
__device__ float g_xattn[(size_t)B_ * C_ * HW_];           // 75.5 MB: attn output, image layout

// ======================= K1: depthwise qkv conv + leaky + stats =============
// grid (6,6, 2*B*C), block (32,8). Each block: one 32x32 tile of one (s,b,c).
__global__ void k1_qkv_conv(const float* __restrict__ x, const float* __restrict__ ir,
                            const float* __restrict__ w, const float* __restrict__ bias)
{
    int zc = blockIdx.z;
    int c = zc & (C_ - 1);
    int b = (zc >> 7) & 3;
    int s = zc >> 9;
    const float* src = (s == 0 ? x : ir) + (size_t)(b * C_ + c) * HW_;

    __shared__ float tile[34][36];
    int tx0 = blockIdx.x * 32, ty0 = blockIdx.y * 32;
    int tid = threadIdx.y * 32 + threadIdx.x;
    for (int i = tid; i < 34 * 34; i += 256) {
        int r = i / 34, q = i - r * 34;
        int gy = ty0 + r - 1, gx = tx0 + q - 1;
        float v = 0.f;
        if (gy >= 0 && gy < H_ && gx >= 0 && gx < W_) v = __ldg(src + gy * W_ + gx);
        tile[r][q] = v;
    }
    __syncthreads();

    float wr[27];
#pragma unroll
    for (int j = 0; j < 27; j++) wr[j] = __ldg(w + c * 27 + j);
    float bz0 = __ldg(bias + c * 3 + 0);
    float bz1 = __ldg(bias + c * 3 + 1);
    float bz2 = __ldg(bias + c * 3 + 2);
    float bz[3] = {bz0, bz1, bz2};

    float sum[3] = {0.f, 0.f, 0.f}, sq[3] = {0.f, 0.f, 0.f};
    float* outbase = g_y + (size_t)((s * B_ + b) * C3_ + c * 3) * HW_;

#pragma unroll
    for (int rr = 0; rr < 4; rr++) {
        int ly = threadIdx.y + rr * 8;
        int lx = threadIdx.x;
        float n[9];
#pragma unroll
        for (int kd = 0; kd < 3; kd++)
#pragma unroll
            for (int kp = 0; kp < 3; kp++)
                n[kd * 3 + kp] = tile[ly + kd][lx + kp];
        size_t pix = (size_t)(ty0 + ly) * W_ + (tx0 + lx);
#pragma unroll
        for (int e = 0; e < 3; e++) {
            float a = bz[e];
#pragma unroll
            for (int j = 0; j < 9; j++) a = fmaf(wr[e * 9 + j], n[j], a);
            a = a > 0.f ? a : 0.05f * a;
            sum[e] += a;
            sq[e]  += a * a;
            outbase[(size_t)e * HW_ + pix] = a;
        }
    }

    __shared__ float rbuf[6][8];
    int lane = tid & 31, wp = tid >> 5;
    float vals[6] = {sum[0], sum[1], sum[2], sq[0], sq[1], sq[2]};
#pragma unroll
    for (int i = 0; i < 6; i++) {
        float v = vals[i];
#pragma unroll
        for (int o = 16; o > 0; o >>= 1) v += __shfl_down_sync(0xffffffffu, v, o);
        if (lane == 0) rbuf[i][wp] = v;
    }
    __syncthreads();
    if (tid < 6) {
        float s2 = 0.f;
#pragma unroll
        for (int i = 0; i < 8; i++) s2 += rbuf[tid][i];
        int e = tid % 3, which = tid / 3;
        int chg = (s * B_ + b) * C3_ + c * 3 + e;
        int tileid = blockIdx.y * 6 + blockIdx.x;
        g_spart[((size_t)chg * NTILE + tileid) * 2 + which] = s2;
    }
}

// ======================= K2: stats -> scale/offset ===========================
__global__ void k2_stats(const float* __restrict__ gamma, const float* __restrict__ beta)
{
    int i = blockIdx.x * blockDim.x + threadIdx.x;
    if (i >= 2 * B_ * C3_) return;
    int ch = i % C3_;
    float s = 0.f, q = 0.f;
    const float* p = g_spart + (size_t)i * NTILE * 2;
#pragma unroll
    for (int t = 0; t < NTILE; t++) { s += p[t * 2]; q += p[t * 2 + 1]; }
    float mu  = s / (float)HW_;
    float var = q / (float)HW_ - mu * mu;
    var = fmaxf(var, 0.f);
    float inv = 1.f / sqrtf(var + 1e-5f);
    float sc  = gamma[ch] * inv;
    g_scale[i] = sc;
    g_off[i]   = beta[ch] - mu * sc;
}

// ======================= K3: q/k/v fusion convs (4ch -> 2ch over D x HW) ====
// grid (HW/64, 4, 3*B), block 256 (64 p-cols x 4 d-quads, 4 rows each).
__global__ void __launch_bounds__(256) k3_fuse_conv(
        const float* __restrict__ wq, const float* __restrict__ bq,
        const float* __restrict__ wk, const float* __restrict__ bk,
        const float* __restrict__ wv, const float* __restrict__ bv)
{
    int e  = blockIdx.z >> 2;       // 0=q,1=k,2=v
    int b  = blockIdx.z & 3;
    int d0 = blockIdx.y * 16;
    int p0 = blockIdx.x * 64;
    const float* wsel = (e == 0) ? wq : ((e == 1) ? wk : wv);
    const float* bsel = (e == 0) ? bq : ((e == 1) ? bk : bv);

    __shared__ float sw[72];
    __shared__ float sbias[2];
    __shared__ float sscale[4][18];
    __shared__ float soff[4][18];
    __shared__ float sm[4][18][66];

    int tid = threadIdx.x;
    if (tid < 72) {
        sw[tid] = wsel[tid];
        int ic = tid / 18, dd = tid - ic * 18;
        int d = d0 + dd - 1;
        float sc = 0.f, of = 0.f;
        if ((unsigned)d < 64u) {
            int st = ic >> 1, hh = ic & 1;
            int sidx = (st * B_ + b) * C3_ + (hh * 64 + d) * 3 + e;
            sc = g_scale[sidx];
            of = g_off[sidx];
        }
        sscale[ic][dd] = sc;
        soff[ic][dd]   = of;
    }
    if (tid < 2) sbias[tid] = bsel[tid];
    __syncthreads();

    for (int i = tid; i < 4 * 18 * 66; i += 256) {
        int ic  = i / (18 * 66);
        int rem = i - ic * (18 * 66);
        int dd  = rem / 66;
        int pp  = rem - dd * 66;
        int d = d0 + dd - 1;
        int p = p0 + pp - 1;
        float v = 0.f;
        if ((unsigned)d < 64u && (unsigned)p < (unsigned)HW_) {
            int st = ic >> 1, hh = ic & 1;
            int ch = (hh * 64 + d) * 3 + e;
            size_t idx = (size_t)((st * B_ + b) * C3_ + ch) * HW_ + p;
            v = fmaf(g_y[idx], sscale[ic][dd], soff[ic][dd]);
        }
        sm[ic][dd][pp] = v;
    }
    __syncthreads();

    int px = tid & 63;
    int dq = tid >> 6;

    float acc0[4], acc1[4];
#pragma unroll
    for (int r = 0; r < 4; r++) { acc0[r] = sbias[0]; acc1[r] = sbias[1]; }

#pragma unroll
    for (int ic = 0; ic < 4; ic++) {
        float w0[9], w1[9];
#pragma unroll
        for (int j = 0; j < 9; j++) { w0[j] = sw[ic * 9 + j]; w1[j] = sw[36 + ic * 9 + j]; }
#pragma unroll
        for (int r = 0; r < 4; r++) {
            int dd = dq * 4 + r;
#pragma unroll
            for (int kd = 0; kd < 3; kd++)
#pragma unroll
                for (int kp = 0; kp < 3; kp++) {
                    float v = sm[ic][dd + kd][px + kp];
                    acc0[r] = fmaf(v, w0[kd * 3 + kp], acc0[r]);
                    acc1[r] = fmaf(v, w1[kd * 3 + kp], acc1[r]);
                }
        }
    }

    size_t base = (size_t)(e * B_ + b) * NH_ * D_ * HW_;
#pragma unroll
    for (int r = 0; r < 4; r++) {
        int d = d0 + dq * 4 + r, p = p0 + px;
        float a0 = acc0[r], a1 = acc1[r];
        a0 = a0 > 0.f ? a0 : 0.05f * a0;
        a1 = a1 > 0.f ? a1 : 0.05f * a1;
        g_qkv[base + (size_t)d * HW_ + p]        = a0;
        g_qkv[base + (size_t)(D_ + d) * HW_ + p] = a1;
    }
}

// ======================= K4b: q/k row L2 norms ===============================
// grid 1024 (= 2 tensors * B*NH*D rows), block 256.
__global__ void k4b_norms()
{
    int flat = blockIdx.x;
    const float4* row = (const float4*)(g_qkv + (size_t)flat * HW_);
    float s = 0.f;
    for (int i = threadIdx.x; i < HW_ / 4; i += 256) {
        float4 v = row[i];
        s += v.x * v.x + v.y * v.y + v.z * v.z + v.w * v.w;
    }
    __shared__ float rb[8];
    int lane = threadIdx.x & 31, wp = threadIdx.x >> 5;
#pragma unroll
    for (int o = 16; o > 0; o >>= 1) s += __shfl_down_sync(0xffffffffu, s, o);
    if (lane == 0) rb[wp] = s;
    __syncthreads();
    if (threadIdx.x == 0) {
        float t = 0.f;
#pragma unroll
        for (int i = 0; i < 8; i++) t += rb[i];
        g_rnorm[flat] = sqrtf(t);
    }
}

// ======================= K4: split-K 64x64 GEMM q.k^T =======================
// grid (NCHUNK, B*NH), block 256. Each thread: 4x4 micro-tile.
__global__ void __launch_bounds__(256) k4_gemm()
{
    int chunk = blockIdx.x, bh = blockIdx.y;
    const float* qb = g_qkv + (size_t)bh * D_ * HW_;
    const float* kb = g_qkv + (size_t)(B_ * NH_ + bh) * D_ * HW_;
    __shared__ float qs[64 * 33], ks[64 * 33];
    int tid = threadIdx.x;
    int tx = tid & 15, ty = tid >> 4;
    float acc[4][4];
#pragma unroll
    for (int i = 0; i < 4; i++)
#pragma unroll
        for (int j = 0; j < 4; j++) acc[i][j] = 0.f;

    int pbase = chunk * CHUNK;
    for (int step = 0; step < CHUNK; step += 32) {
#pragma unroll
        for (int i = 0; i < 8; i++) {
            int idx = tid + i * 256;
            int r = idx >> 5, cc = idx & 31;
            size_t off = (size_t)r * HW_ + pbase + step + cc;
            qs[r * 33 + cc] = qb[off];
            ks[r * 33 + cc] = kb[off];
        }
        __syncthreads();
#pragma unroll 8
        for (int kk = 0; kk < 32; kk++) {
            float a[4], bb[4];
#pragma unroll
            for (int i = 0; i < 4; i++) a[i]  = qs[(ty * 4 + i) * 33 + kk];
#pragma unroll
            for (int i = 0; i < 4; i++) bb[i] = ks[(tx * 4 + i) * 33 + kk];
#pragma unroll
            for (int i = 0; i < 4; i++)
#pragma unroll
                for (int j = 0; j < 4; j++)
                    acc[i][j] = fmaf(a[i], bb[j], acc[i][j]);
        }
        __syncthreads();
    }
    float* outp = g_part + ((size_t)chunk * (B_ * NH_) + bh) * 4096;
#pragma unroll
    for (int i = 0; i < 4; i++)
#pragma unroll
        for (int j = 0; j < 4; j++)
            outp[(ty * 4 + i) * 64 + (tx * 4 + j)] = acc[i][j];
}

// ======================= K5: reduce partials + normalize + softmax ==========
// grid B*NH*D rows, block 64 threads (one per column e).
__global__ void k5_softmax(const float* __restrict__ tin)
{
    int row = blockIdx.x;      // = bh*64 + d
    int d  = row & 63;
    int bh = row >> 6;
    int h  = bh & 1;
    int e  = threadIdx.x;

    float raw = 0.f;
#pragma unroll
    for (int ck = 0; ck < NCHUNK; ck++)
        raw += g_part[(((size_t)ck * (B_ * NH_) + bh) * 64 + d) * 64 + e];

    float nq = fmaxf(g_rnorm[bh * 64 + d], 1e-12f);
    float nk = fmaxf(g_rnorm[(B_ * NH_) * 64 + bh * 64 + e], 1e-12f);
    float a = raw / (nq * nk) * tin[h];

    __shared__ float sbuf[64];
    sbuf[e] = a;
    __syncthreads();
    float m = -1e30f;
#pragma unroll
    for (int i = 0; i < 64; i++) m = fmaxf(m, sbuf[i]);
    __syncthreads();
    float ex = expf(a - m);
    sbuf[e] = ex;
    __syncthreads();
    float ssum = 0.f;
#pragma unroll
    for (int i = 0; i < 64; i++) ssum += sbuf[i];
    g_attn[(size_t)row * 64 + e] = ex / ssum;
}

// ======================= K6: attn @ v, write in image layout ================
// grid (HW/256, B*NH), block 256. Thread = 1 p column, 64 accumulators.
__global__ void __launch_bounds__(256) k6_av()
{
    int bh = blockIdx.y;
    int b = bh >> 1, h = bh & 1;
    __shared__ float at[64 * 64];
    int tid = threadIdx.x;
    const float4* asrc = (const float4*)(g_attn + (size_t)bh * 4096);
#pragma unroll
    for (int i = 0; i < 4; i++)
        ((float4*)at)[tid + i * 256] = asrc[tid + i * 256];
    __syncthreads();

    int p = blockIdx.x * 256 + tid;
    const float* vb = g_qkv + (size_t)(2 * B_ * NH_ + bh) * D_ * HW_ + p;

    float acc[64];
#pragma unroll
    for (int d = 0; d < 64; d++) acc[d] = 0.f;

#pragma unroll 1
    for (int e = 0; e < 64; e += 4) {
        float v0 = vb[(size_t)(e + 0) * HW_];
        float v1 = vb[(size_t)(e + 1) * HW_];
        float v2 = vb[(size_t)(e + 2) * HW_];
        float v3 = vb[(size_t)(e + 3) * HW_];
#pragma unroll
        for (int d = 0; d < 64; d++) {
            float4 a = *(const float4*)(at + d * 64 + e);
            acc[d] = fmaf(a.x, v0, acc[d]);
            acc[d] = fmaf(a.y, v1, acc[d]);
            acc[d] = fmaf(a.z, v2, acc[d]);
            acc[d] = fmaf(a.w, v3, acc[d]);
        }
    }

    float* ob = g_xattn + (size_t)b * C_ * HW_ + p;
#pragma unroll
    for (int d = 0; d < 64; d++)
        ob[(size_t)(d * 2 + h) * HW_] = acc[d];   // channel = d*NH + h
}

// ======================= K7: final depthwise conv + leaky ====================
// grid (6,6, B*C), block (32,8).
__global__ void k7_fus(const float* __restrict__ w, const float* __restrict__ bias,
                       float* __restrict__ out)
{
    int zc = blockIdx.z;
    int c = zc & (C_ - 1);
    int b = zc >> 7;
    const float* src = g_xattn + (size_t)(b * C_ + c) * HW_;

    __shared__ float tile[34][36];
    int tx0 = blockIdx.x * 32, ty0 = blockIdx.y * 32;
    int tid = threadIdx.y * 32 + threadIdx.x;
    for (int i = tid; i < 34 * 34; i += 256) {
        int r = i / 34, q = i - r * 34;
        int gy = ty0 + r - 1, gx = tx0 + q - 1;
        float v = 0.f;
        if (gy >= 0 && gy < H_ && gx >= 0 && gx < W_) v = src[gy * W_ + gx];
        tile[r][q] = v;
    }
    __syncthreads();

    float wr[9];
#pragma unroll
    for (int j = 0; j < 9; j++) wr[j] = __ldg(w + c * 9 + j);
    float bb = __ldg(bias + c);
    float* ob = out + (size_t)(b * C_ + c) * HW_;

#pragma unroll
    for (int rr = 0; rr < 4; rr++) {
        int ly = threadIdx.y + rr * 8, lx = threadIdx.x;
        float a = bb;
#pragma unroll
        for (int kd = 0; kd < 3; kd++)
#pragma unroll
            for (int kp = 0; kp < 3; kp++)
                a = fmaf(tile[ly + kd][lx + kp], wr[kd * 3 + kp], a);
        a = a > 0.f ? a : 0.05f * a;
        ob[(size_t)(ty0 + ly) * W_ + (tx0 + lx)] = a;
    }
}

// ======================= launcher ===========================================
extern "C" void kernel_launch(void* const* d_in, const int* in_sizes, int n_in,
                              void* d_out, int out_size)
{
    const float* x      = (const float*)d_in[0];
    const float* ir     = (const float*)d_in[1];
    const float* w_qkv  = (const float*)d_in[2];
    const float* b_qkv  = (const float*)d_in[3];
    const float* gamma  = (const float*)d_in[4];
    const float* beta   = (const float*)d_in[5];
    const float* wq     = (const float*)d_in[6];
    const float* bq     = (const float*)d_in[7];
    const float* wk     = (const float*)d_in[8];
    const float* bk     = (const float*)d_in[9];
    const float* wv     = (const float*)d_in[10];
    const float* bv     = (const float*)d_in[11];
    const float* t      = (const float*)d_in[12];
    const float* w_fus  = (const float*)d_in[13];
    const float* b_fus  = (const float*)d_in[14];
    float* out = (float*)d_out;

    dim3 blk2d(32, 8);

    k1_qkv_conv<<<dim3(6, 6, 2 * B_ * C_), blk2d>>>(x, ir, w_qkv, b_qkv);
    k2_stats<<<(2 * B_ * C3_ + 255) / 256, 256>>>(gamma, beta);
    k3_fuse_conv<<<dim3(HW_ / 64, 4, 3 * B_), 256>>>(wq, bq, wk, bk, wv, bv);
    k4b_norms<<<2 * B_ * NH_ * D_, 256>>>();
    k4_gemm<<<dim3(NCHUNK, B_ * NH_), 256>>>();
    k5_softmax<<<B_ * NH_ * D_, 64>>>(t);
    k6_av<<<dim3(HW_ / 256, B_ * NH_), 256>>>();
    k7_fus<<<dim3(6, 6, B_ * C_), blk2d>>>(w_fus, b_fus, out);
}

// round 15
// speedup vs baseline: 1.0777x; 1.0777x over previous
#include <cuda_runtime.h>
#include <math.h>

// Problem constants
#define B_  4
#define C_  128
#define H_  192
#define W_  192
#define HW_ (H_ * W_)          // 36864
#define NH_ 2
#define D_  64
#define C3_ 384                 // 3 * C
#define NCHUNK 64
#define CHUNK  (HW_ / NCHUNK)   // 576
#define NTILE  36               // 6x6 tiles of 32x32
#define PT  32                  // K3 p-tile

// ---------------- scratch (device globals; no allocation allowed) -----------
__device__ float g_spart[2 * B_ * C3_ * NTILE * 2];        // per-tile (sum, sumsq)
__device__ float g_scale[2 * B_ * C3_];                    // instancenorm scale
__device__ float g_off[2 * B_ * C3_];                      // instancenorm offset
__device__ float g_qkv[(size_t)3 * B_ * NH_ * D_ * HW_];   // 226 MB: q,k,v after fusion convs
__device__ float g_part[(size_t)NCHUNK * B_ * NH_ * D_ * D_]; // 8 MB: split-K GEMM partials
__device__ float g_npart[(size_t)NCHUNK * B_ * NH_ * 2 * D_]; // per-chunk sumsq partials (q,k)
__device__ float g_attn[B_ * NH_ * D_ * D_];               // softmaxed attention
__device__ float g_xattn[(size_t)B_ * C_ * HW_];           // 75.5 MB: attn output, image layout

// ======================= K1: depthwise qkv conv + leaky -> STATS ONLY =======
// grid (6,6, 2*B*C), block (32,8). Each block: one 32x32 tile of one (s,b,c).
// No y store — y is recomputed bit-exactly in K3.
__global__ void k1_qkv_stats(const float* __restrict__ x, const float* __restrict__ ir,
                             const float* __restrict__ w, const float* __restrict__ bias)
{
    int zc = blockIdx.z;
    int c = zc & (C_ - 1);
    int b = (zc >> 7) & 3;
    int s = zc >> 9;
    const float* src = (s == 0 ? x : ir) + (size_t)(b * C_ + c) * HW_;

    __shared__ float tile[34][36];
    int tx0 = blockIdx.x * 32, ty0 = blockIdx.y * 32;
    int tid = threadIdx.y * 32 + threadIdx.x;
    for (int i = tid; i < 34 * 34; i += 256) {
        int r = i / 34, q = i - r * 34;
        int gy = ty0 + r - 1, gx = tx0 + q - 1;
        float v = 0.f;
        if (gy >= 0 && gy < H_ && gx >= 0 && gx < W_) v = __ldg(src + gy * W_ + gx);
        tile[r][q] = v;
    }
    __syncthreads();

    float wr[27];
#pragma unroll
    for (int j = 0; j < 27; j++) wr[j] = __ldg(w + c * 27 + j);
    float bz[3];
#pragma unroll
    for (int e = 0; e < 3; e++) bz[e] = __ldg(bias + c * 3 + e);

    float sum[3] = {0.f, 0.f, 0.f}, sq[3] = {0.f, 0.f, 0.f};

#pragma unroll
    for (int rr = 0; rr < 4; rr++) {
        int ly = threadIdx.y + rr * 8;
        int lx = threadIdx.x;
        float n[9];
#pragma unroll
        for (int kd = 0; kd < 3; kd++)
#pragma unroll
            for (int kp = 0; kp < 3; kp++)
                n[kd * 3 + kp] = tile[ly + kd][lx + kp];
#pragma unroll
        for (int e = 0; e < 3; e++) {
            float a = bz[e];
#pragma unroll
            for (int j = 0; j < 9; j++) a = fmaf(wr[e * 9 + j], n[j], a);
            a = a > 0.f ? a : 0.05f * a;
            sum[e] += a;
            sq[e]  += a * a;
        }
    }

    __shared__ float rbuf[6][8];
    int lane = tid & 31, wp = tid >> 5;
    float vals[6] = {sum[0], sum[1], sum[2], sq[0], sq[1], sq[2]};
#pragma unroll
    for (int i = 0; i < 6; i++) {
        float v = vals[i];
#pragma unroll
        for (int o = 16; o > 0; o >>= 1) v += __shfl_down_sync(0xffffffffu, v, o);
        if (lane == 0) rbuf[i][wp] = v;
    }
    __syncthreads();
    if (tid < 6) {
        float s2 = 0.f;
#pragma unroll
        for (int i = 0; i < 8; i++) s2 += rbuf[tid][i];
        int e = tid % 3, which = tid / 3;
        int chg = (s * B_ + b) * C3_ + c * 3 + e;
        int tileid = blockIdx.y * 6 + blockIdx.x;
        g_spart[((size_t)chg * NTILE + tileid) * 2 + which] = s2;
    }
}

// ======================= K2: stats -> scale/offset ===========================
__global__ void k2_stats(const float* __restrict__ gamma, const float* __restrict__ beta)
{
    int i = blockIdx.x * blockDim.x + threadIdx.x;
    if (i >= 2 * B_ * C3_) return;
    int ch = i % C3_;
    float s = 0.f, q = 0.f;
    const float* p = g_spart + (size_t)i * NTILE * 2;
#pragma unroll
    for (int t = 0; t < NTILE; t++) { s += p[t * 2]; q += p[t * 2 + 1]; }
    float mu  = s / (float)HW_;
    float var = q / (float)HW_ - mu * mu;
    var = fmaxf(var, 0.f);
    float inv = 1.f / sqrtf(var + 1e-5f);
    float sc  = gamma[ch] * inv;
    g_scale[i] = sc;
    g_off[i]   = beta[ch] - mu * sc;
}

// ======================= K3: recompute y + q/k/v fusion convs ===============
// grid (HW/PT, 4, B), block 256. One block: all of q,k,v for (b, 16 d-rows, PT p-cols).
// y = affine(leaky(depthwise3x3(x))) recomputed in staging (bit-exact vs old g_y).
__global__ void __launch_bounds__(256) k3_fuse_conv(
        const float* __restrict__ x,  const float* __restrict__ ir,
        const float* __restrict__ w_qkv, const float* __restrict__ b_qkv,
        const float* __restrict__ wq, const float* __restrict__ bq,
        const float* __restrict__ wk, const float* __restrict__ bk,
        const float* __restrict__ wv, const float* __restrict__ bv)
{
    int b  = blockIdx.z;
    int d0 = blockIdx.y * 16;
    int p0 = blockIdx.x * PT;

    __shared__ float sy[3][4][18][PT + 4];     // y tiles per e; pp in 0..PT+1
    __shared__ float swt[2][18][3][12];        // [hh][dd][e][w0..w8, bias]
    __shared__ float ssc[4][18][3], sof[4][18][3];
    __shared__ float sfw[3][2][4][9];          // fusion weights [e][outch][ic][9]
    __shared__ float sfb[3][2];

    int tid = threadIdx.x;

    // depthwise weights + bias (shared across streams)
    for (int i = tid; i < 2 * 18 * 3; i += 256) {
        int hh = i / 54; int rem = i - hh * 54; int dd = rem / 3; int e = rem - dd * 3;
        int d = d0 + dd - 1;
        if ((unsigned)d < 64u) {
            int g = (hh * 64 + d) * 3 + e;
#pragma unroll
            for (int j = 0; j < 9; j++) swt[hh][dd][e][j] = __ldg(w_qkv + g * 9 + j);
            swt[hh][dd][e][9] = __ldg(b_qkv + g);
        } else {
#pragma unroll
            for (int j = 0; j < 10; j++) swt[hh][dd][e][j] = 0.f;
        }
    }
    // instancenorm scale/offset (stream-dependent)
    for (int i = tid; i < 4 * 18 * 3; i += 256) {
        int ic = i / 54; int rem = i - ic * 54; int dd = rem / 3; int e = rem - dd * 3;
        int d = d0 + dd - 1;
        float sc = 0.f, of = 0.f;
        if ((unsigned)d < 64u) {
            int st = ic >> 1, hh = ic & 1;
            int sidx = (st * B_ + b) * C3_ + (hh * 64 + d) * 3 + e;
            sc = g_scale[sidx];
            of = g_off[sidx];
        }
        ssc[ic][dd][e] = sc;
        sof[ic][dd][e] = of;
    }
    // fusion conv weights
    if (tid < 3 * 2 * 4 * 9) {
        int e = tid / 72; int rem = tid - e * 72;
        int oc = rem / 36; int rem2 = rem - oc * 36;
        int icc = rem2 / 9; int j = rem2 - icc * 9;
        const float* ws = (e == 0) ? wq : ((e == 1) ? wk : wv);
        sfw[e][oc][icc][j] = __ldg(ws + (oc * 4 + icc) * 9 + j);
    }
    if (tid < 6) {
        int e = tid >> 1, oc = tid & 1;
        const float* bs = (e == 0) ? bq : ((e == 1) ? bk : bv);
        sfb[e][oc] = __ldg(bs + oc);
    }
    __syncthreads();

    // ---- staging: recompute y for all 3 e's -------------------------------
    for (int i = tid; i < 4 * 18 * (PT + 2); i += 256) {
        int ic  = i / (18 * (PT + 2));
        int rem = i - ic * (18 * (PT + 2));
        int dd  = rem / (PT + 2);
        int pp  = rem - dd * (PT + 2);
        int d = d0 + dd - 1;
        int p = p0 + pp - 1;
        float v0 = 0.f, v1 = 0.f, v2 = 0.f;
        if ((unsigned)d < 64u && (unsigned)p < (unsigned)HW_) {
            int st = ic >> 1, hh = ic & 1;
            int c = hh * 64 + d;
            const float* src = (st ? ir : x) + (size_t)(b * C_ + c) * HW_;
            int py = p / W_;
            int px = p - py * W_;
            float t[9];
#pragma unroll
            for (int kd = 0; kd < 3; kd++) {
                int yy = py + kd - 1;
#pragma unroll
                for (int kp = 0; kp < 3; kp++) {
                    int xx = px + kp - 1;
                    float vv = 0.f;
                    if ((unsigned)yy < (unsigned)H_ && (unsigned)xx < (unsigned)W_)
                        vv = __ldg(src + yy * W_ + xx);
                    t[kd * 3 + kp] = vv;
                }
            }
#pragma unroll
            for (int e = 0; e < 3; e++) {
                float a = swt[hh][dd][e][9];
#pragma unroll
                for (int j = 0; j < 9; j++) a = fmaf(swt[hh][dd][e][j], t[j], a);
                a = a > 0.f ? a : 0.05f * a;
                a = fmaf(a, ssc[ic][dd][e], sof[ic][dd][e]);
                if (e == 0) v0 = a; else if (e == 1) v1 = a; else v2 = a;
            }
        }
        sy[0][ic][dd][pp] = v0;
        sy[1][ic][dd][pp] = v1;
        sy[2][ic][dd][pp] = v2;
    }
    __syncthreads();

    // ---- fusion convs ------------------------------------------------------
    int px = tid & (PT - 1);
    int dg = tid >> 5;            // 0..7, two d-rows each

#pragma unroll
    for (int e = 0; e < 3; e++) {
        float acc0[2] = {sfb[e][0], sfb[e][0]};
        float acc1[2] = {sfb[e][1], sfb[e][1]};
#pragma unroll
        for (int icc = 0; icc < 4; icc++) {
            float w0[9], w1[9];
#pragma unroll
            for (int j = 0; j < 9; j++) { w0[j] = sfw[e][0][icc][j]; w1[j] = sfw[e][1][icc][j]; }
#pragma unroll
            for (int r = 0; r < 2; r++) {
                int od = dg * 2 + r;
#pragma unroll
                for (int kd = 0; kd < 3; kd++)
#pragma unroll
                    for (int kp = 0; kp < 3; kp++) {
                        float v = sy[e][icc][od + kd][px + kp];
                        acc0[r] = fmaf(v, w0[kd * 3 + kp], acc0[r]);
                        acc1[r] = fmaf(v, w1[kd * 3 + kp], acc1[r]);
                    }
            }
        }
        size_t base = (size_t)(e * B_ + b) * NH_ * D_ * HW_;
#pragma unroll
        for (int r = 0; r < 2; r++) {
            int d = d0 + dg * 2 + r, p = p0 + px;
            float a0 = acc0[r], a1 = acc1[r];
            a0 = a0 > 0.f ? a0 : 0.05f * a0;
            a1 = a1 > 0.f ? a1 : 0.05f * a1;
            g_qkv[base + (size_t)d * HW_ + p]        = a0;
            g_qkv[base + (size_t)(D_ + d) * HW_ + p] = a1;
        }
    }
}

// ======================= K4: split-K 64x64 GEMM q.k^T + norm partials =======
// grid (NCHUNK, B*NH), block 256. Each thread: 4x4 micro-tile.
__global__ void __launch_bounds__(256) k4_gemm()
{
    int chunk = blockIdx.x, bh = blockIdx.y;
    const float* qb = g_qkv + (size_t)bh * D_ * HW_;
    const float* kb = g_qkv + (size_t)(B_ * NH_ + bh) * D_ * HW_;
    __shared__ float qs[64 * 33], ks[64 * 33];
    int tid = threadIdx.x;
    int tx = tid & 15, ty = tid >> 4;
    float acc[4][4];
#pragma unroll
    for (int i = 0; i < 4; i++)
#pragma unroll
        for (int j = 0; j < 4; j++) acc[i][j] = 0.f;

    float qsqA[8], ksqA[8];
#pragma unroll
    for (int i = 0; i < 8; i++) { qsqA[i] = 0.f; ksqA[i] = 0.f; }

    int pbase = chunk * CHUNK;
    for (int step = 0; step < CHUNK; step += 32) {
#pragma unroll
        for (int i = 0; i < 8; i++) {
            int idx = tid + i * 256;
            int r = idx >> 5, cc = idx & 31;
            size_t off = (size_t)r * HW_ + pbase + step + cc;
            float qv = qb[off], kv = kb[off];
            qs[r * 33 + cc] = qv;
            ks[r * 33 + cc] = kv;
            qsqA[i] = fmaf(qv, qv, qsqA[i]);
            ksqA[i] = fmaf(kv, kv, ksqA[i]);
        }
        __syncthreads();
#pragma unroll 8
        for (int kk = 0; kk < 32; kk++) {
            float a[4], bb[4];
#pragma unroll
            for (int i = 0; i < 4; i++) a[i]  = qs[(ty * 4 + i) * 33 + kk];
#pragma unroll
            for (int i = 0; i < 4; i++) bb[i] = ks[(tx * 4 + i) * 33 + kk];
#pragma unroll
            for (int i = 0; i < 4; i++)
#pragma unroll
                for (int j = 0; j < 4; j++)
                    acc[i][j] = fmaf(a[i], bb[j], acc[i][j]);
        }
        __syncthreads();
    }
    float* outp = g_part + ((size_t)chunk * (B_ * NH_) + bh) * 4096;
#pragma unroll
    for (int i = 0; i < 4; i++)
#pragma unroll
        for (int j = 0; j < 4; j++)
            outp[(ty * 4 + i) * 64 + (tx * 4 + j)] = acc[i][j];

    // per-row sum-of-squares partials: warp w owns rows w + 8i (all lanes same row)
    int lane = tid & 31, wrp = tid >> 5;
#pragma unroll
    for (int i = 0; i < 8; i++) {
        float a = qsqA[i], c = ksqA[i];
#pragma unroll
        for (int o = 16; o > 0; o >>= 1) {
            a += __shfl_down_sync(0xffffffffu, a, o);
            c += __shfl_down_sync(0xffffffffu, c, o);
        }
        if (lane == 0) {
            int row = wrp + i * 8;
            g_npart[(((size_t)chunk * (B_ * NH_) + bh) * 2 + 0) * 64 + row] = a;
            g_npart[(((size_t)chunk * (B_ * NH_) + bh) * 2 + 1) * 64 + row] = c;
        }
    }
}

// ======================= K5: reduce partials + normalize + softmax ==========
// grid B*NH*D rows, block 64 threads (one per column e).
__global__ void k5_softmax(const float* __restrict__ tin)
{
    int row = blockIdx.x;      // = bh*64 + d
    int d  = row & 63;
    int bh = row >> 6;
    int h  = bh & 1;
    int e  = threadIdx.x;

    float raw = 0.f, sq_q = 0.f, sq_k = 0.f;
#pragma unroll 8
    for (int ck = 0; ck < NCHUNK; ck++) {
        raw  += g_part[(((size_t)ck * (B_ * NH_) + bh) * 64 + d) * 64 + e];
        sq_q += g_npart[(((size_t)ck * (B_ * NH_) + bh) * 2 + 0) * 64 + d];
        sq_k += g_npart[(((size_t)ck * (B_ * NH_) + bh) * 2 + 1) * 64 + e];
    }

    float nq = fmaxf(sqrtf(sq_q), 1e-12f);
    float nk = fmaxf(sqrtf(sq_k), 1e-12f);
    float a = raw / (nq * nk) * tin[h];

    __shared__ float sbuf[64];
    sbuf[e] = a;
    __syncthreads();
    float m = -1e30f;
#pragma unroll
    for (int i = 0; i < 64; i++) m = fmaxf(m, sbuf[i]);
    __syncthreads();
    float ex = expf(a - m);
    sbuf[e] = ex;
    __syncthreads();
    float ssum = 0.f;
#pragma unroll
    for (int i = 0; i < 64; i++) ssum += sbuf[i];
    g_attn[(size_t)row * 64 + e] = ex / ssum;
}

// ======================= K6: attn @ v, write in image layout ================
// grid (HW/256, B*NH), block 256. Thread = 1 p column, 64 accumulators.
__global__ void __launch_bounds__(256) k6_av()
{
    int bh = blockIdx.y;
    int b = bh >> 1, h = bh & 1;
    __shared__ float at[64 * 64];
    int tid = threadIdx.x;
    const float4* asrc = (const float4*)(g_attn + (size_t)bh * 4096);
#pragma unroll
    for (int i = 0; i < 4; i++)
        ((float4*)at)[tid + i * 256] = asrc[tid + i * 256];
    __syncthreads();

    int p = blockIdx.x * 256 + tid;
    const float* vb = g_qkv + (size_t)(2 * B_ * NH_ + bh) * D_ * HW_ + p;

    float acc[64];
#pragma unroll
    for (int d = 0; d < 64; d++) acc[d] = 0.f;

#pragma unroll 1
    for (int e = 0; e < 64; e += 4) {
        float v0 = vb[(size_t)(e + 0) * HW_];
        float v1 = vb[(size_t)(e + 1) * HW_];
        float v2 = vb[(size_t)(e + 2) * HW_];
        float v3 = vb[(size_t)(e + 3) * HW_];
#pragma unroll
        for (int d = 0; d < 64; d++) {
            float4 a = *(const float4*)(at + d * 64 + e);
            acc[d] = fmaf(a.x, v0, acc[d]);
            acc[d] = fmaf(a.y, v1, acc[d]);
            acc[d] = fmaf(a.z, v2, acc[d]);
            acc[d] = fmaf(a.w, v3, acc[d]);
        }
    }

    float* ob = g_xattn + (size_t)b * C_ * HW_ + p;
#pragma unroll
    for (int d = 0; d < 64; d++)
        ob[(size_t)(d * 2 + h) * HW_] = acc[d];   // channel = d*NH + h
}

// ======================= K7: final depthwise conv + leaky ====================
// grid (6,6, B*C), block (32,8).
__global__ void k7_fus(const float* __restrict__ w, const float* __restrict__ bias,
                       float* __restrict__ out)
{
    int zc = blockIdx.z;
    int c = zc & (C_ - 1);
    int b = zc >> 7;
    const float* src = g_xattn + (size_t)(b * C_ + c) * HW_;

    __shared__ float tile[34][36];
    int tx0 = blockIdx.x * 32, ty0 = blockIdx.y * 32;
    int tid = threadIdx.y * 32 + threadIdx.x;
    for (int i = tid; i < 34 * 34; i += 256) {
        int r = i / 34, q = i - r * 34;
        int gy = ty0 + r - 1, gx = tx0 + q - 1;
        float v = 0.f;
        if (gy >= 0 && gy < H_ && gx >= 0 && gx < W_) v = src[gy * W_ + gx];
        tile[r][q] = v;
    }
    __syncthreads();

    float wr[9];
#pragma unroll
    for (int j = 0; j < 9; j++) wr[j] = __ldg(w + c * 9 + j);
    float bb = __ldg(bias + c);
    float* ob = out + (size_t)(b * C_ + c) * HW_;

#pragma unroll
    for (int rr = 0; rr < 4; rr++) {
        int ly = threadIdx.y + rr * 8, lx = threadIdx.x;
        float a = bb;
#pragma unroll
        for (int kd = 0; kd < 3; kd++)
#pragma unroll
            for (int kp = 0; kp < 3; kp++)
                a = fmaf(tile[ly + kd][lx + kp], wr[kd * 3 + kp], a);
        a = a > 0.f ? a : 0.05f * a;
        ob[(size_t)(ty0 + ly) * W_ + (tx0 + lx)] = a;
    }
}

// ======================= launcher ===========================================
extern "C" void kernel_launch(void* const* d_in, const int* in_sizes, int n_in,
                              void* d_out, int out_size)
{
    const float* x      = (const float*)d_in[0];
    const float* ir     = (const float*)d_in[1];
    const float* w_qkv  = (const float*)d_in[2];
    const float* b_qkv  = (const float*)d_in[3];
    const float* gamma  = (const float*)d_in[4];
    const float* beta   = (const float*)d_in[5];
    const float* wq     = (const float*)d_in[6];
    const float* bq     = (const float*)d_in[7];
    const float* wk     = (const float*)d_in[8];
    const float* bk     = (const float*)d_in[9];
    const float* wv     = (const float*)d_in[10];
    const float* bv     = (const float*)d_in[11];
    const float* t      = (const float*)d_in[12];
    const float* w_fus  = (const float*)d_in[13];
    const float* b_fus  = (const float*)d_in[14];
    float* out = (float*)d_out;

    dim3 blk2d(32, 8);

    k1_qkv_stats<<<dim3(6, 6, 2 * B_ * C_), blk2d>>>(x, ir, w_qkv, b_qkv);
    k2_stats<<<(2 * B_ * C3_ + 255) / 256, 256>>>(gamma, beta);
    k3_fuse_conv<<<dim3(HW_ / PT, 4, B_), 256>>>(x, ir, w_qkv, b_qkv,
                                                 wq, bq, wk, bk, wv, bv);
    k4_gemm<<<dim3(NCHUNK, B_ * NH_), 256>>>();
    k5_softmax<<<B_ * NH_ * D_, 64>>>(t);
    k6_av<<<dim3(HW_ / 256, B_ * NH_), 256>>>();
    k7_fus<<<dim3(6, 6, B_ * C_), blk2d>>>(w_fus, b_fus, out);
}